// round 2
// baseline (speedup 1.0000x reference)
#include <cuda_runtime.h>
#include <math.h>

// Problem constants (fixed by setup_inputs / reference)
#define MPI_HH 300
#define MPI_WW 400
#define MPI_DD 24
#define GRID_H 4
#define GRID_W 6
#define ATL_C 16
#define ATL_H 1200
#define ATL_W 2400
#define IMG_H 240
#define IMG_W 320
#define NPIX (IMG_H * IMG_W)
#define NEAR_D 2.0f
#define FAR_D 100.0f
#define CX_MPI 200.0f   // 160 + (400-320)/2
#define CY_MPI 150.0f   // 120 + (300-240)/2
#define REF_F 300.0f

#define HID 48
#define FEAT_C 16

// Packed constant layout (floats):
//   [0      .. 960)   : per-hidden-unit rows [j][20] = { w1[0:16, j], w2[j, 0:4] }
//   [960    .. 2304)  : vemb rows [j][28] = { w1[16:43, j], pad }
//   [2304   .. 2352)  : b1[48]
//   [2352   .. 2356)  : b2[4]
#define OFF_W1F  0
#define OFF_W1V  960
#define OFF_B1   2304
#define OFF_B2   2352
#define PACK_N   2368

__device__  __align__(16) float g_pack[PACK_N];
__constant__ __align__(16) float c_pack[PACK_N];

__global__ void prep_pack_kernel(const float* __restrict__ w1,
                                 const float* __restrict__ b1,
                                 const float* __restrict__ w2,
                                 const float* __restrict__ b2)
{
    const int t = threadIdx.x;
    const int stride = blockDim.x;
    // w1 feat part + w2, interleaved per hidden unit: [j][20]
    for (int idx = t; idx < HID * 20; idx += stride) {
        const int j = idx / 20;
        const int q = idx - j * 20;
        g_pack[OFF_W1F + idx] = (q < 16) ? w1[q * HID + j] : w2[j * 4 + (q - 16)];
    }
    // w1 vemb part transposed: [j][28], pad cols 27 with 0
    for (int idx = t; idx < HID * 28; idx += stride) {
        const int j = idx / 28;
        const int i = idx - j * 28;
        g_pack[OFF_W1V + idx] = (i < 27) ? w1[(16 + i) * HID + j] : 0.0f;
    }
    for (int idx = t; idx < HID; idx += stride) g_pack[OFF_B1 + idx] = b1[idx];
    if (t < 4) g_pack[OFF_B2 + t] = b2[t];
}

__global__ __launch_bounds__(128, 4)
void mpi_render_kernel(const float* __restrict__ extrin,
                       const float* __restrict__ intrin,
                       const float* __restrict__ atlas,
                       float* __restrict__ out)
{
    const int pix = blockIdx.x * blockDim.x + threadIdx.x;
    if (pix >= NPIX) return;
    const int yi = pix / IMG_W;
    const int xi = pix - yi * IMG_W;

    // ---------------- Per-pixel geometry ----------------
    const float R00 = extrin[0],  R01 = extrin[1],  R02 = extrin[2],  T0 = extrin[3];
    const float R10 = extrin[4],  R11 = extrin[5],  R12 = extrin[6],  T1 = extrin[7];
    const float R20 = extrin[8],  R21 = extrin[9],  R22 = extrin[10], T2 = extrin[11];

    const float cox = -(R00 * T0 + R10 * T1 + R20 * T2);
    const float coy = -(R01 * T0 + R11 * T1 + R21 * T2);
    const float coz = -(R02 * T0 + R12 * T1 + R22 * T2);

    const float ka = intrin[0], kb = intrin[1], kc = intrin[2];
    const float kd = intrin[3], ke = intrin[4], kf = intrin[5];
    const float kg = intrin[6], kh = intrin[7], ki = intrin[8];
    const float det = ka * (ke * ki - kf * kh)
                    - kb * (kd * ki - kf * kg)
                    + kc * (kd * kh - ke * kg);
    const float idet = 1.0f / det;
    const float i00 = (ke * ki - kf * kh) * idet;
    const float i01 = (kc * kh - kb * ki) * idet;
    const float i02 = (kb * kf - kc * ke) * idet;
    const float i10 = (kf * kg - kd * ki) * idet;
    const float i11 = (ka * ki - kc * kg) * idet;
    const float i12 = (kc * kd - ka * kf) * idet;
    const float i20 = (kd * kh - ke * kg) * idet;
    const float i21 = (kb * kg - ka * kh) * idet;
    const float i22 = (ka * ke - kb * kd) * idet;

    const float pxf = (float)xi;
    const float pyf = (float)yi;
    const float dc0 = i00 * pxf + i01 * pyf + i02;
    const float dc1 = i10 * pxf + i11 * pyf + i12;
    const float dc2 = i20 * pxf + i21 * pyf + i22;

    const float dwx = R00 * dc0 + R10 * dc1 + R20 * dc2;
    const float dwy = R01 * dc0 + R11 * dc1 + R21 * dc2;
    const float dwz = R02 * dc0 + R12 * dc1 + R22 * dc2;

    const float invn = 1.0f / sqrtf(dwx * dwx + dwy * dwy + dwz * dwz);
    const float vx = dwx * invn, vy = dwy * invn, vz = dwz * invn;

    float vemb[28];
    vemb[0] = vx; vemb[1] = vy; vemb[2] = vz;
    #pragma unroll
    for (int kk = 0; kk < 4; kk++) {
        const float sc = (float)(1 << kk);
        vemb[3 + 6 * kk + 0] = sinf(vx * sc);
        vemb[3 + 6 * kk + 1] = sinf(vy * sc);
        vemb[3 + 6 * kk + 2] = sinf(vz * sc);
        vemb[3 + 6 * kk + 3] = cosf(vx * sc);
        vemb[3 + 6 * kk + 4] = cosf(vy * sc);
        vemb[3 + 6 * kk + 5] = cosf(vz * sc);
    }
    vemb[27] = 0.0f;

    // Per-pixel partial layer-1 from constant memory (uniform-port loads)
    float g[HID];
    #pragma unroll
    for (int j = 0; j < HID; j++) {
        float acc = c_pack[OFF_B1 + j];
        #pragma unroll
        for (int q = 0; q < 7; q++) {
            const float4 wv = *(const float4*)&c_pack[OFF_W1V + j * 28 + q * 4];
            acc += wv.x * vemb[4 * q + 0] + wv.y * vemb[4 * q + 1]
                 + wv.z * vemb[4 * q + 2] + wv.w * vemb[4 * q + 3];
        }
        g[j] = acc;
    }

    // ---------------- Plane loop (front-to-back: k = 23 .. 0) ----------------
    const float inv_near = 1.0f / NEAR_D;
    const float inv_far  = 1.0f / FAR_D;
    const float dstep = (inv_far - inv_near) / (float)(MPI_DD - 1);
    const float invdz = 1.0f / dwz;
    const float bb0 = c_pack[OFF_B2 + 0], bb1 = c_pack[OFF_B2 + 1];
    const float bb2 = c_pack[OFF_B2 + 2], bb3 = c_pack[OFF_B2 + 3];

    float Tt = 1.0f;
    float orr = 0.0f, ogg = 0.0f, obb = 0.0f;

    #pragma unroll 1
    for (int k = MPI_DD - 1; k >= 0; --k) {
        const float depth = 1.0f / (inv_near + (float)(MPI_DD - 1 - k) * dstep);
        const float t = (depth - coz) * invdz;
        const float pz = coz + t * dwz;
        const float ipz = 1.0f / pz;
        const float pxv = (cox + t * dwx) * ipz * REF_F + CX_MPI;
        const float pyv = (coy + t * dwy) * ipz * REF_F + CY_MPI;

        const bool valid = (t > 0.0f)
                        && (pxv >= 0.0f) && (pxv <= (float)(MPI_WW - 1))
                        && (pyv >= 0.0f) && (pyv <= (float)(MPI_HH - 1));

        // clamp (reference clips regardless of validity)
        const float pxc = fminf(fmaxf(pxv, 0.0f), (float)(MPI_WW - 1));
        const float pyc = fminf(fmaxf(pyv, 0.0f), (float)(MPI_HH - 1));

        const int colk = k % GRID_W;
        const int rowk = k / GRID_W;
        const float ax = ((float)colk + pxc / (float)(MPI_WW - 1)) * ((float)(ATL_W - 1) / (float)GRID_W);
        const float ay = ((float)rowk + pyc / (float)(MPI_HH - 1)) * ((float)(ATL_H - 1) / (float)GRID_H);

        const float fx0 = floorf(ax);
        const float fy0 = floorf(ay);
        const int x0 = (int)fx0;
        const int y0 = (int)fy0;
        const int x1 = min(x0 + 1, ATL_W - 1);
        const int y1 = min(y0 + 1, ATL_H - 1);
        const float wx = ax - fx0;
        const float wy = ay - fy0;

        const int o00 = y0 * ATL_W + x0;
        const int o01 = y0 * ATL_W + x1;
        const int o10 = y1 * ATL_W + x0;
        const int o11 = y1 * ATL_W + x1;

        float feat[FEAT_C];
        #pragma unroll
        for (int cc = 0; cc < FEAT_C; cc++) {
            const float* p = atlas + cc * (ATL_H * ATL_W);
            const float a00 = __ldg(p + o00);
            const float a01 = __ldg(p + o01);
            const float a10 = __ldg(p + o10);
            const float a11 = __ldg(p + o11);
            const float top = fmaf(wx, a01 - a00, a00);
            const float bot = fmaf(wx, a11 - a10, a10);
            feat[cc] = fmaf(wy, bot - top, top);
        }

        float s0 = bb0, s1 = bb1, s2 = bb2, s3 = bb3;
        #pragma unroll
        for (int j = 0; j < HID; j++) {
            const float4 w0 = *(const float4*)&c_pack[OFF_W1F + j * 20 + 0];
            const float4 w1v = *(const float4*)&c_pack[OFF_W1F + j * 20 + 4];
            const float4 w2v = *(const float4*)&c_pack[OFF_W1F + j * 20 + 8];
            const float4 w3v = *(const float4*)&c_pack[OFF_W1F + j * 20 + 12];
            const float4 wo  = *(const float4*)&c_pack[OFF_W1F + j * 20 + 16];
            float hj = g[j];
            hj += w0.x * feat[0]  + w0.y * feat[1]  + w0.z * feat[2]  + w0.w * feat[3];
            hj += w1v.x * feat[4]  + w1v.y * feat[5]  + w1v.z * feat[6]  + w1v.w * feat[7];
            hj += w2v.x * feat[8]  + w2v.y * feat[9]  + w2v.z * feat[10] + w2v.w * feat[11];
            hj += w3v.x * feat[12] + w3v.y * feat[13] + w3v.z * feat[14] + w3v.w * feat[15];
            hj = fmaxf(hj, 0.0f);
            s0 = fmaf(hj, wo.x, s0);
            s1 = fmaf(hj, wo.y, s1);
            s2 = fmaf(hj, wo.z, s2);
            s3 = fmaf(hj, wo.w, s3);
        }

        const float cr = 1.0f / (1.0f + __expf(-s0));
        const float cg = 1.0f / (1.0f + __expf(-s1));
        const float cb = 1.0f / (1.0f + __expf(-s2));
        float al = 1.0f / (1.0f + __expf(-s3));
        al = valid ? al : 0.0f;

        const float wgt = al * Tt;
        orr = fmaf(cr, wgt, orr);
        ogg = fmaf(cg, wgt, ogg);
        obb = fmaf(cb, wgt, obb);
        Tt *= (1.0f - al);
    }

    out[pix * 3 + 0] = orr;
    out[pix * 3 + 1] = ogg;
    out[pix * 3 + 2] = obb;
}

extern "C" void kernel_launch(void* const* d_in, const int* in_sizes, int n_in,
                              void* d_out, int out_size)
{
    const float* extrin = nullptr;
    const float* intrin = nullptr;
    const float* atlas  = nullptr;
    const float* w1 = nullptr;
    const float* b1 = nullptr;
    const float* w2 = nullptr;
    const float* b2 = nullptr;
    for (int i = 0; i < n_in; i++) {
        switch (in_sizes[i]) {
            case 16:        extrin = (const float*)d_in[i]; break;
            case 9:         intrin = (const float*)d_in[i]; break;
            case ATL_C * ATL_H * ATL_W: atlas = (const float*)d_in[i]; break;
            case 43 * HID:  w1 = (const float*)d_in[i]; break;
            case HID:       b1 = (const float*)d_in[i]; break;
            case HID * 4:   w2 = (const float*)d_in[i]; break;
            case 4:         b2 = (const float*)d_in[i]; break;
            default: break;
        }
    }
    float* out = (float*)d_out;

    // 1) Pack/transpose weights into device scratch (deterministic, capturable)
    prep_pack_kernel<<<1, 256>>>(w1, b1, w2, b2);

    // 2) Copy scratch into constant memory (D2D async memcpy — capturable)
    void* src = nullptr;
    cudaGetSymbolAddress(&src, g_pack);
    cudaMemcpyToSymbolAsync(c_pack, src, PACK_N * sizeof(float), 0,
                            cudaMemcpyDeviceToDevice, 0);

    // 3) Main render
    const int threads = 128;
    const int grid = (NPIX + threads - 1) / threads;
    mpi_render_kernel<<<grid, threads>>>(extrin, intrin, atlas, out);
}